// round 15
// baseline (speedup 1.0000x reference)
#include <cuda_runtime.h>

#define B_ROWS 16384
#define IN_DIM 2048
#define E_NUM 16
#define KMAX 8

#define TEMP_F 0.7f
#define P_MIN_F 0.92f
#define CLOSE_F 0.82f   // P_MIN - CLOSE_DELTA

#define SC_OFF (B_ROWS * KMAX)          // 131072
#define MK_OFF (2 * B_ROWS * KMAX)      // 262144
#define KV_OFF (3 * B_ROWS * KMAX)      // 393216

#define THREADS 512
#define RPP 8                           // rows per pass
#define NPASS (B_ROWS / RPP)            // 2048
#define NBLOCKS 148
#define XBUF_FLOATS (RPP * IN_DIM)      // 16384 floats = 64 KB

__device__ int g_pass_counter;
__global__ void reset_counter_kernel() { g_pass_counter = 0; }

__device__ __forceinline__ void cp_async16(unsigned saddr, const void* gaddr) {
    asm volatile("cp.async.cg.shared.global [%0], [%1], 16;" :: "r"(saddr), "l"(gaddr));
}
__device__ __forceinline__ void cp_commit() {
    asm volatile("cp.async.commit_group;");
}
__device__ __forceinline__ void cp_wait0() {
    asm volatile("cp.async.wait_group 0;");
}

// stage one 8-row x pass (4096 float4 granules / 512 threads)
__device__ __forceinline__ void stage_pass(float* xs, const float* x, int p, int tid) {
    unsigned sb = (unsigned)__cvta_generic_to_shared(xs);
    const float4* src = reinterpret_cast<const float4*>(x + (size_t)p * RPP * IN_DIM);
#pragma unroll
    for (int i = 0; i < 8; i++) {
        int idx = tid + i * THREADS;
        cp_async16(sb + idx * 16, src + idx);
    }
}

#define FMA4(e, xv)                                                           \
    acc[(e) * 8 + r] = fmaf(Wv[e][jj].x, (xv).x, acc[(e) * 8 + r]);           \
    acc[(e) * 8 + r] = fmaf(Wv[e][jj].y, (xv).y, acc[(e) * 8 + r]);           \
    acc[(e) * 8 + r] = fmaf(Wv[e][jj].z, (xv).z, acc[(e) * 8 + r]);           \
    acc[(e) * 8 + r] = fmaf(Wv[e][jj].w, (xv).w, acc[(e) * 8 + r]);

__global__ __launch_bounds__(THREADS, 1) void dyn_top_gate_kernel(
    const float* __restrict__ x,
    const float* __restrict__ W1,
    const float* __restrict__ W2,
    float* __restrict__ out)
{
    extern __shared__ __align__(16) float sm[];
    float* xs0  = sm;                       // 16384
    float* xs1  = sm + XBUF_FLOATS;         // 16384
    float* sred = sm + 2 * XBUF_FLOATS;     // 512
    float* sh   = sred + 512;               // 128
    int*   spass = (int*)(sh + 128);

    const int tid  = threadIdx.x;
    const int lane = tid & 31;
    const int wid  = tid >> 5;              // 0..15
    const int eg   = wid >> 2;              // expert group (4 experts)
    const int kq   = wid & 3;               // K quarter (512 floats)

    // ---- W1 slice resident in registers: Wv[e][j] = W1[eg*4+e][kq*512+j*128+lane*4]
    float4 Wv[4][4];
#pragma unroll
    for (int e = 0; e < 4; e++)
#pragma unroll
        for (int j = 0; j < 4; j++)
            Wv[e][j] = __ldg(reinterpret_cast<const float4*>(
                W1 + (size_t)(eg * 4 + e) * IN_DIM + kq * 512 + j * 128 + lane * 4));

    // ---- prologue: steal pass 0 and 1, stage pass 0 ------------------------
    if (tid == 0) spass[0] = atomicAdd(&g_pass_counter, 1);
    __syncthreads();
    int p_cur = spass[0];
    if (p_cur < NPASS) stage_pass(xs0, x, p_cur, tid);
    cp_commit();
    __syncthreads();
    if (tid == 0) spass[0] = atomicAdd(&g_pass_counter, 1);
    cp_wait0();
    __syncthreads();
    int p_next = spass[0];

    float* bufA = xs0;
    float* bufB = xs1;

    while (p_cur < NPASS) {
        // stage next pass into the other buffer (overlaps with compute below)
        if (p_next < NPASS) stage_pass(bufB, x, p_next, tid);
        cp_commit();

        // ---- compute: acc[e*8+r] partial over this lane's 16 K-floats ----
        float acc[32];
#pragma unroll
        for (int i = 0; i < 32; i++) acc[i] = 0.f;

        const float* xb = bufA + kq * 512 + lane * 4;
#pragma unroll
        for (int r = 0; r < RPP; r++) {
            const float* xrb = xb + r * IN_DIM;
            float4 xv0 = *reinterpret_cast<const float4*>(xrb);
            float4 xv1 = *reinterpret_cast<const float4*>(xrb + 128);
            {   const int jj = 0; FMA4(0, xv0) FMA4(1, xv0) FMA4(2, xv0) FMA4(3, xv0) }
            float4 xv2 = *reinterpret_cast<const float4*>(xrb + 256);
            {   const int jj = 1; FMA4(0, xv1) FMA4(1, xv1) FMA4(2, xv1) FMA4(3, xv1) }
            float4 xv3 = *reinterpret_cast<const float4*>(xrb + 384);
            {   const int jj = 2; FMA4(0, xv2) FMA4(1, xv2) FMA4(2, xv2) FMA4(3, xv2) }
            {   const int jj = 3; FMA4(0, xv3) FMA4(1, xv3) FMA4(2, xv3) FMA4(3, xv3) }
        }

        // ---- butterfly: 32 slots -> lane l holds full warp sum of slot l --
        // slot = e*8 + r  (e = lane>>3, r = lane&7 at the end)
#pragma unroll
        for (int off = 16, cnt = 32; off >= 1; off >>= 1, cnt >>= 1) {
            const bool up = (lane & off) != 0;
#pragma unroll
            for (int i = 0; i < cnt / 2; i++) {
                float send = up ? acc[i] : acc[i + cnt / 2];
                float keep = up ? acc[i + cnt / 2] : acc[i];
                float recv = __shfl_xor_sync(0xffffffffu, send, off);
                acc[i] = keep + recv;
            }
        }
        sred[wid * 32 + lane] = acc[0];
        __syncthreads();                                 // bar A: sred ready

        if (tid == 0) spass[0] = atomicAdd(&g_pass_counter, 1);
        if (tid < 128) {
            const int teg = tid >> 5, tl = tid & 31;
            float s = sred[(teg * 4 + 0) * 32 + tl] + sred[(teg * 4 + 1) * 32 + tl]
                    + sred[(teg * 4 + 2) * 32 + tl] + sred[(teg * 4 + 3) * 32 + tl];
            // e_local = tl>>3, r = tl&7 ; global expert = teg*4 + e_local
            sh[(tl & 7) * 16 + teg * 4 + (tl >> 3)] = tanhf(s);
        }
        cp_wait0();                                      // next x staged (mine)
        __syncthreads();                                 // bar B: sh + x visible

        // ---- epilogue on warps 0-1 (others race ahead into next compute) --
        if (wid < 2) {
            const int g = lane >> 4;
            const int f = lane & 15;
#pragma unroll
            for (int rr = 0; rr < 2; rr++) {
                const int rloc = wid * 4 + 2 * g + rr;   // 0..7
                const int row = p_cur * RPP + rloc;
                const float th = sh[rloc * 16 + f];

                float logit = 0.f;
#pragma unroll
                for (int e = 0; e < E_NUM; e++) {
                    float hv = __shfl_sync(0xffffffffu, th, (lane & 16) | e);
                    logit = fmaf(hv, __ldg(W2 + f * E_NUM + e), logit);
                }
                logit = logit / TEMP_F;

                float m = logit;
#pragma unroll
                for (int s2 = 8; s2 > 0; s2 >>= 1)
                    m = fmaxf(m, __shfl_xor_sync(0xffffffffu, m, s2, 16));

                float ex = expf(logit - m);
                float sum = ex;
#pragma unroll
                for (int s2 = 8; s2 > 0; s2 >>= 1)
                    sum += __shfl_xor_sync(0xffffffffu, sum, s2, 16);
                float prob = ex / sum;

                int rank = 0;
#pragma unroll
                for (int g2 = 0; g2 < E_NUM; g2++) {
                    float lv = __shfl_sync(0xffffffffu, logit, g2, 16);
                    rank += (lv > logit) || (lv == logit && g2 < f);
                }

                float cum = 0.f, p1 = 0.f, p2 = 0.f, p3 = 0.f;
#pragma unroll
                for (int g2 = 0; g2 < E_NUM; g2++) {
                    float pv = __shfl_sync(0xffffffffu, prob, g2, 16);
                    int rv = __shfl_sync(0xffffffffu, rank, g2, 16);
                    if (rv <= rank) cum += pv;
                    if (rv == 0) p1 = pv;
                    if (rv == 1) p2 = pv;
                    if (rv == 2) p3 = pv;
                }

                int cnt2 = 0;
#pragma unroll
                for (int g2 = 0; g2 < E_NUM; g2++) {
                    float cv = __shfl_sync(0xffffffffu, cum, g2, 16);
                    cnt2 += (cv < P_MIN_F);
                }
                if (cnt2 > E_NUM - 1) cnt2 = E_NUM - 1;
                int kv = cnt2 + 1;

                float gap12 = p1 - p2;
                float gap23 = p2 - p3;
                if (p1 >= 0.46f && gap12 >= 0.1f) kv = 1;
                float cum1 = p1 + p2;
                if (kv > 2 && (cum1 >= CLOSE_F || p3 <= 0.12f || gap23 <= 0.03f)) kv = 2;
                kv = max(1, min(3, kv));

                if (rank < KMAX) {
                    int o = row * KMAX + rank;
                    out[o] = (float)f;                              // top_indices
                    out[SC_OFF + o] = (rank < kv) ? prob : 0.f;     // top_scores
                    out[MK_OFF + o] = (rank < kv) ? 1.f : 0.f;      // top_mask
                }
                if (rank == 0) out[KV_OFF + row] = (float)kv;       // k_vec
            }
        }

        // ---- rotate ------------------------------------------------------
        float* t = bufA; bufA = bufB; bufB = t;
        p_cur = p_next;
        p_next = spass[0];      // stolen in this pass's barA->barB window
    }
}

extern "C" void kernel_launch(void* const* d_in, const int* in_sizes, int n_in,
                              void* d_out, int out_size) {
    const float* x  = (const float*)d_in[0];
    const float* W1 = (const float*)d_in[1];
    const float* W2 = (const float*)d_in[2];
    float* out = (float*)d_out;

    const int smem_bytes = (2 * XBUF_FLOATS + 512 + 128 + 4) * 4;   // ~131.6 KB
    static int attr_set = 0;
    if (!attr_set) {
        cudaFuncSetAttribute(dyn_top_gate_kernel,
                             cudaFuncAttributeMaxDynamicSharedMemorySize,
                             smem_bytes);
        attr_set = 1;
    }

    reset_counter_kernel<<<1, 1>>>();
    dyn_top_gate_kernel<<<NBLOCKS, THREADS, smem_bytes>>>(x, W1, W2, out);
}

// round 17
// speedup vs baseline: 1.3231x; 1.3231x over previous
#include <cuda_runtime.h>

#define B_ROWS 16384
#define IN_DIM 2048
#define E_NUM 16
#define KMAX 8

#define TEMP_F 0.7f
#define P_MIN_F 0.92f
#define CLOSE_F 0.82f   // P_MIN - CLOSE_DELTA

#define SC_OFF (B_ROWS * KMAX)          // 131072
#define MK_OFF (2 * B_ROWS * KMAX)      // 262144
#define KV_OFF (3 * B_ROWS * KMAX)      // 393216

#define THREADS 512
#define NBLOCKS 148
#define RPT 8                           // rows per warp-tile
#define NTILES (B_ROWS / RPT)           // 2048
#define NBODY 32                        // bodies of 64 K-floats
// smem layout (floats)
#define SW_FLOATS 32768                 // W1 permuted: 128 KB
#define SX_OFF 32768                    // x: 16 warps * 2 bufs * 512 floats
#define SX_PER_WARP 1024                // floats (2 bufs * 512)
#define SH_OFF (SX_OFF + 16 * SX_PER_WARP)   // 49152: h scratch 16*128 floats
#define SM_FLOATS (SH_OFF + 16 * 128)        // 51200 floats = 204800 B

__device__ __forceinline__ void cp_async16(unsigned saddr, const void* gaddr) {
    asm volatile("cp.async.cg.shared.global [%0], [%1], 16;" :: "r"(saddr), "l"(gaddr));
}
__device__ __forceinline__ void cp_commit() {
    asm volatile("cp.async.commit_group;");
}
__device__ __forceinline__ void cp_wait1() {
    asm volatile("cp.async.wait_group 1;");
}
__device__ __forceinline__ void cp_wait2() {
    asm volatile("cp.async.wait_group 2;");
}

__global__ __launch_bounds__(THREADS, 1) void dyn_top_gate_kernel(
    const float* __restrict__ x,
    const float* __restrict__ W1,
    const float* __restrict__ W2,
    float* __restrict__ out)
{
    extern __shared__ __align__(16) float sm[];

    const int tid  = threadIdx.x;
    const int lane = tid & 31;
    const int wid  = tid >> 5;                  // 0..15
    const int lh   = lane & 15;                 // lane within half
    const int hh   = lane >> 4;                 // expert half (0/1)

    // static per-SM tile range: block b gets [b*2048/148, (b+1)*2048/148)
    const int t1   = (int)(((unsigned)(blockIdx.x + 1) * NTILES) / NBLOCKS);
    const int myt  = (int)(((unsigned)blockIdx.x * NTILES) / NBLOCKS) + wid;
    const bool active = myt < t1;

    // ---- stage W1, permuted: granule g=(el*512+kq)*2+h  <-  W1[h*8+el][4kq..]
    {
        unsigned wsb = (unsigned)__cvta_generic_to_shared(sm);
#pragma unroll
        for (int i = 0; i < 16; i++) {
            int g  = tid + i * THREADS;          // 0..8191
            int h_ = g & 1;
            int kq = (g >> 1) & 511;
            int el = g >> 10;
            cp_async16(wsb + g * 16, W1 + (h_ * 8 + el) * IN_DIM + kq * 4);
        }
        cp_commit();
    }

    // per-warp x buffers
    float* xbuf = sm + SX_OFF + wid * SX_PER_WARP;
    unsigned xsb = (unsigned)__cvta_generic_to_shared(xbuf);
    const float* xrow = x + (size_t)myt * RPT * IN_DIM;

    // stage one body (8 rows x 64 floats): 128 granules, 4 per lane
#define STAGE_X(buf, b)                                                       \
    {                                                                         \
        _Pragma("unroll")                                                     \
        for (int j = 0; j < 4; j++) {                                         \
            int gi = lane + j * 32;              /* 0..127 */                 \
            int r_ = gi >> 4, q_ = gi & 15;                                   \
            cp_async16(xsb + (buf) * 2048 + gi * 16,                          \
                       xrow + (size_t)r_ * IN_DIM + (b) * 64 + q_ * 4);       \
        }                                                                     \
    }

    if (active) STAGE_X(0, 0);
    cp_commit();
    if (active) STAGE_X(1, 1);
    cp_commit();
    cp_wait2();                                  // own W1 granules done
    __syncthreads();                             // ALL W1 granules visible

    if (active) {
        float acc[64];                           // acc[el*8 + r]
#pragma unroll
        for (int i = 0; i < 64; i++) acc[i] = 0.f;

        // lane-fixed W pointer: + el*16384B + body*512B
        const char* wlane = (const char*)sm + lh * 32 + hh * 16;

        int buf = 0;
        int bodyoff = 0;                         // body * 512 bytes
#pragma unroll 1
        for (int b = 0; b < NBODY; b++) {
            cp_wait1();                          // body b staged (per-lane)
            __syncwarp();                        // cross-lane visibility

            const float* xb = xbuf + buf * 512;
            float4 xv[RPT];
#pragma unroll
            for (int r = 0; r < RPT; r++)
                xv[r] = *reinterpret_cast<const float4*>(xb + r * 64 + lh * 4);

#pragma unroll
            for (int el = 0; el < 8; el++) {
                float4 w = *reinterpret_cast<const float4*>(
                    wlane + el * 16384 + bodyoff);
#pragma unroll
                for (int r = 0; r < RPT; r++) {
                    acc[el * 8 + r] = fmaf(w.x, xv[r].x, acc[el * 8 + r]);
                    acc[el * 8 + r] = fmaf(w.y, xv[r].y, acc[el * 8 + r]);
                    acc[el * 8 + r] = fmaf(w.z, xv[r].z, acc[el * 8 + r]);
                    acc[el * 8 + r] = fmaf(w.w, xv[r].w, acc[el * 8 + r]);
                }
            }

            if (b + 2 < NBODY) STAGE_X(buf, b + 2);
            cp_commit();                         // empty commit ok on tail
            buf ^= 1;
            bodyoff += 512;
        }

        // ---- butterfly within 16-lane half: 64 slots -> 4 per lane --------
        // final: lane (hh,lh) holds slots s = 4*lh + j, s = el*8 + r
#pragma unroll
        for (int off = 8, cnt = 64; off >= 1; off >>= 1, cnt >>= 1) {
            const bool up = (lane & off) != 0;
#pragma unroll
            for (int i = 0; i < cnt / 2; i++) {
                float send = up ? acc[i] : acc[i + cnt / 2];
                float keep = up ? acc[i + cnt / 2] : acc[i];
                float recv = __shfl_xor_sync(0xffffffffu, send, off);
                acc[i] = keep + recv;
            }
        }

        // ---- tanh + stash h into per-warp scratch: shw[r*16 + e] ----------
        float* shw = sm + SH_OFF + wid * 128;
#pragma unroll
        for (int j = 0; j < 4; j++) {
            int s = 4 * lh + j;
            shw[(s & 7) * 16 + hh * 8 + (s >> 3)] = tanhf(acc[j]);
        }
        __syncwarp();

        // ---- epilogue: lane = f + 16*g ; rows 2j+g -----------------------
        const int g = lane >> 4;
        const int f = lane & 15;

        float w2f[E_NUM];
#pragma unroll
        for (int e = 0; e < E_NUM; e++) w2f[e] = __ldg(W2 + f * E_NUM + e);

#pragma unroll
        for (int j = 0; j < 4; j++) {
            const int rloc = 2 * j + g;
            const int row = myt * RPT + rloc;

            // logit from smem h (broadcast within segment)
            float logit = 0.f;
#pragma unroll
            for (int e = 0; e < E_NUM; e++)
                logit = fmaf(shw[rloc * 16 + e], w2f[e], logit);
            logit = logit / TEMP_F;

            // softmax over 16-lane segment
            float m = logit;
#pragma unroll
            for (int s2 = 8; s2 > 0; s2 >>= 1)
                m = fmaxf(m, __shfl_xor_sync(0xffffffffu, m, s2, 16));

            float ex = expf(logit - m);
            float sum = ex;
#pragma unroll
            for (int s2 = 8; s2 > 0; s2 >>= 1)
                sum += __shfl_xor_sync(0xffffffffu, sum, s2, 16);
            float prob = ex / sum;

            // stable descending rank (ties -> smaller expert index first)
            int rank = 0;
#pragma unroll
            for (int g2 = 0; g2 < E_NUM; g2++) {
                float lv = __shfl_sync(0xffffffffu, logit, g2, 16);
                rank += (lv > logit) || (lv == logit && g2 < f);
            }

            // inclusive cumulative prob at my rank; pick p1,p2,p3
            float cum = 0.f, p1 = 0.f, p2 = 0.f, p3 = 0.f;
#pragma unroll
            for (int g2 = 0; g2 < E_NUM; g2++) {
                float pv = __shfl_sync(0xffffffffu, prob, g2, 16);
                int rv = __shfl_sync(0xffffffffu, rank, g2, 16);
                if (rv <= rank) cum += pv;
                if (rv == 0) p1 = pv;
                if (rv == 1) p2 = pv;
                if (rv == 2) p3 = pv;
            }

            // idx_first = #ranks with cum < P_MIN (cum monotone in rank)
            int cnt2 = 0;
#pragma unroll
            for (int g2 = 0; g2 < E_NUM; g2++) {
                float cv = __shfl_sync(0xffffffffu, cum, g2, 16);
                cnt2 += (cv < P_MIN_F);
            }
            if (cnt2 > E_NUM - 1) cnt2 = E_NUM - 1;
            int kv = cnt2 + 1;

            float gap12 = p1 - p2;
            float gap23 = p2 - p3;
            if (p1 >= 0.46f && gap12 >= 0.1f) kv = 1;
            float cum1 = p1 + p2;
            if (kv > 2 && (cum1 >= CLOSE_F || p3 <= 0.12f || gap23 <= 0.03f)) kv = 2;
            kv = max(1, min(3, kv));

            // ----- writes -----
            if (rank < KMAX) {
                int o = row * KMAX + rank;
                out[o] = (float)f;                               // top_indices
                out[SC_OFF + o] = (rank < kv) ? prob : 0.f;      // top_scores
                out[MK_OFF + o] = (rank < kv) ? 1.f : 0.f;       // top_mask
            }
            if (rank == 0) out[KV_OFF + row] = (float)kv;        // k_vec
        }
    }
}

extern "C" void kernel_launch(void* const* d_in, const int* in_sizes, int n_in,
                              void* d_out, int out_size) {
    const float* x  = (const float*)d_in[0];
    const float* W1 = (const float*)d_in[1];
    const float* W2 = (const float*)d_in[2];
    float* out = (float*)d_out;

    const int smem_bytes = SM_FLOATS * 4;      // 204800
    static int attr_set = 0;
    if (!attr_set) {
        cudaFuncSetAttribute(dyn_top_gate_kernel,
                             cudaFuncAttributeMaxDynamicSharedMemorySize,
                             smem_bytes);
        attr_set = 1;
    }

    dyn_top_gate_kernel<<<NBLOCKS, THREADS, smem_bytes>>>(x, W1, W2, out);
}